// round 4
// baseline (speedup 1.0000x reference)
#include <cuda_runtime.h>
#include <cstdint>

#define BB 8
#define NN 8192
#define CF 64
#define SS 1024
#define KK 32
#define NPOS (BB*SS*KK)   // 262144

// ---------------- scratch (device globals: allocation-free) ----------------
__device__ float  g_featT[(size_t)BB*NN*CF];      // 16 MB  feat transposed [b][n][c]
__device__ int    g_idx[NPOS];                    // ball query result [b][s][k]
__device__ float  g_y0[(size_t)NPOS*64];          // 67 MB
__device__ float  g_y1[(size_t)NPOS*64];          // 67 MB
__device__ float  g_y2[(size_t)NPOS*128];         // 134 MB
__device__ double g_sum[3*128];
__device__ double g_sumsq[3*128];
__device__ float  g_scale[3*128];
__device__ float  g_shift[3*128];
// spatially-permuted copies for FPS pruning (perm affects speed only, never output)
__device__ float  g_px[BB*NN], g_py[BB*NN], g_pz[BB*NN];
__device__ int    g_perm[BB*NN];                  // permuted pos -> original index
__device__ int    g_start[BB];                    // permuted pos of original index 0

// ---------------- f32x2 packed helpers (bitwise == scalar RN) ----------------
__device__ __forceinline__ unsigned long long pk2(float lo, float hi){
    unsigned long long r; asm("mov.b64 %0, {%1, %2};" : "=l"(r) : "f"(lo), "f"(hi)); return r;
}
__device__ __forceinline__ unsigned long long add2(unsigned long long a, unsigned long long b){
    unsigned long long r; asm("add.rn.f32x2 %0, %1, %2;" : "=l"(r) : "l"(a), "l"(b)); return r;
}
__device__ __forceinline__ unsigned long long mul2(unsigned long long a, unsigned long long b){
    unsigned long long r; asm("mul.rn.f32x2 %0, %1, %2;" : "=l"(r) : "l"(a), "l"(b)); return r;
}
__device__ __forceinline__ void upk2(float& lo, float& hi, unsigned long long v){
    asm("mov.b64 {%0, %1}, %2;" : "=f"(lo), "=f"(hi) : "l"(v));
}

// ---------------- feature transpose: (B,C,N) -> (B,N,C) ----------------
__global__ void transposeK(const float* __restrict__ feat){
    __shared__ float tile[32][33];
    int b = blockIdx.z;
    int n0 = blockIdx.x*32, c0 = blockIdx.y*32;
    int tx = threadIdx.x, ty = threadIdx.y;
    #pragma unroll
    for (int i = ty; i < 32; i += 8)
        tile[i][tx] = feat[((size_t)b*CF + c0 + i)*NN + n0 + tx];
    __syncthreads();
    #pragma unroll
    for (int i = ty; i < 32; i += 8)
        g_featT[((size_t)b*NN + n0 + i)*CF + c0 + tx] = tile[tx][i];
}

// ---------------- spatial bucketing (Morton 8x8x8) for FPS pruning ----------------
__device__ __forceinline__ int mortonCell(float x, float y, float z){
    int ix = min(7, max(0, (int)(x*8.0f)));
    int iy = min(7, max(0, (int)(y*8.0f)));
    int iz = min(7, max(0, (int)(z*8.0f)));
    auto sp = [](int v){ return (v&1) | ((v&2)<<2) | ((v&4)<<4); };
    return (sp(ix)<<2) | (sp(iy)<<1) | sp(iz);
}

__global__ void __launch_bounds__(512) bucketK(const float* __restrict__ xyz){
    __shared__ int hist[512];
    __shared__ int offs[512];
    int b = blockIdx.x, tid = threadIdx.x;
    hist[tid] = 0;
    __syncthreads();
    for (int i = tid; i < NN; i += 512){
        const float* p = &xyz[((size_t)b*NN + i)*3];
        atomicAdd(&hist[mortonCell(p[0], p[1], p[2])], 1);
    }
    __syncthreads();
    int acc = 0;                                  // exclusive prefix (O(tid) scan, once)
    for (int j = 0; j < tid; j++) acc += hist[j];
    offs[tid] = acc;
    __syncthreads();
    for (int i = tid; i < NN; i += 512){
        const float* p = &xyz[((size_t)b*NN + i)*3];
        float x = p[0], y = p[1], z = p[2];
        int pos = atomicAdd(&offs[mortonCell(x, y, z)], 1);
        g_px[b*NN + pos] = x; g_py[b*NN + pos] = y; g_pz[b*NN + pos] = z;
        g_perm[b*NN + pos] = i;
        if (i == 0) g_start[b] = pos;
    }
}

// ---------------- FPS: one CTA per batch, 256 thr x 32 contiguous pts, pruned ----------------
__global__ void __launch_bounds__(256, 1) fpsK(float* __restrict__ outXyz){
    extern __shared__ float sm[];
    float* sx = sm; float* sy = sm + NN; float* sz = sm + 2*NN;
    int*   sPerm = (int*)(sm + 3*NN);
    __shared__ float wmax[8];
    __shared__ int   sArg[2];
    int b = blockIdx.x, tid = threadIdx.x, lane = tid & 31, wid = tid >> 5;

    for (int i = tid; i < NN; i += 256){          // coalesced permuted load
        sx[i] = g_px[b*NN + i];
        sy[i] = g_py[b*NN + i];
        sz[i] = g_pz[b*NN + i];
        sPerm[i] = g_perm[b*NN + i];
    }
    if (tid == 0){ sArg[0] = 0x7fffffff; sArg[1] = 0x7fffffff; }
    __syncthreads();

    // each thread owns 32 CONTIGUOUS permuted points (spatially compact by Morton order)
    unsigned long long px2[16], py2[16], pz2[16];
    float dst[32];
    float mnx = 1e9f, mxx = -1e9f, mny = 1e9f, mxy = -1e9f, mnz = 1e9f, mxz = -1e9f;
    #pragma unroll
    for (int j = 0; j < 16; j++){
        int i0 = tid*32 + 2*j;
        float x0 = sx[i0], y0 = sy[i0], z0 = sz[i0];
        float x1 = sx[i0+1], y1 = sy[i0+1], z1 = sz[i0+1];
        px2[j] = pk2(x0, x1); py2[j] = pk2(y0, y1); pz2[j] = pk2(z0, z1);
        dst[2*j] = 1e10f; dst[2*j+1] = 1e10f;
        mnx = fminf(mnx, fminf(x0, x1)); mxx = fmaxf(mxx, fmaxf(x0, x1));
        mny = fminf(mny, fminf(y0, y1)); mxy = fmaxf(mxy, fmaxf(y0, y1));
        mnz = fminf(mnz, fminf(z0, z1)); mxz = fmaxf(mxz, fmaxf(z0, z1));
    }
    // bounding sphere of owned points (conservative, inflated)
    float mx = 0.5f*(mnx+mxx), my = 0.5f*(mny+mxy), mz = 0.5f*(mnz+mxz);
    float r2m = 0.0f;
    #pragma unroll
    for (int j = 0; j < 16; j++){
        float xl, xh, yl, yh, zl, zh;
        upk2(xl, xh, px2[j]); upk2(yl, yh, py2[j]); upk2(zl, zh, pz2[j]);
        float dl = fmaf(xl-mx, xl-mx, fmaf(yl-my, yl-my, (zl-mz)*(zl-mz)));
        float dh = fmaf(xh-mx, xh-mx, fmaf(yh-my, yh-my, (zh-mz)*(zh-mz)));
        r2m = fmaxf(r2m, fmaxf(dl, dh));
    }
    float rInfl = sqrtf(r2m)*1.0005f + 1e-6f;

    int cur = g_start[b];
    float myBest = 1e10f;
    for (int s = 0; s < SS; s++){
        float cx = sx[cur], cy = sy[cur], cz = sz[cur];
        if (tid == 0){
            outXyz[((size_t)b*SS + s)*3 + 0] = cx;
            outXyz[((size_t)b*SS + s)*3 + 1] = cy;
            outXyz[((size_t)b*SS + s)*3 + 2] = cz;
        }
        // conservative skip test: every owned point provably farther than myBest
        float dxm = cx - mx, dym = cy - my, dzm = cz - mz;
        float sC = sqrtf(fmaf(dxm, dxm, fmaf(dym, dym, dzm*dzm)));
        float L = sC - rInfl;
        bool skip = (L > 0.0f) && (L*L*0.9995f > myBest);
        if (!__all_sync(0xffffffffu, skip)){
            // (p - c) computed as p + (-c): negation exact, rounding == subtraction
            unsigned long long ncx2 = pk2(-cx, -cx);
            unsigned long long ncy2 = pk2(-cy, -cy);
            unsigned long long ncz2 = pk2(-cz, -cz);
            float mb = -1.0f;
            #pragma unroll
            for (int j = 0; j < 16; j++){
                unsigned long long dx2 = add2(px2[j], ncx2);
                unsigned long long dy2 = add2(py2[j], ncy2);
                unsigned long long dz2 = add2(pz2[j], ncz2);
                unsigned long long qx = mul2(dx2, dx2);
                unsigned long long qy = mul2(dy2, dy2);
                unsigned long long qz = mul2(dz2, dz2);
                unsigned long long dd = add2(add2(qx, qy), qz); // ((x^2+y^2)+z^2), RN, no FMA
                float dlo, dhi; upk2(dlo, dhi, dd);
                dst[2*j]   = fminf(dst[2*j],   dlo);
                dst[2*j+1] = fminf(dst[2*j+1], dhi);
                mb = fmaxf(mb, fmaxf(dst[2*j], dst[2*j+1]));
            }
            myBest = mb;          // exact max(dst); if skipped, stale value is still exact
        }
        // warp max in one instruction (dists >= 0 -> uint order == float order)
        unsigned wm = __reduce_max_sync(0xffffffffu, __float_as_uint(myBest));
        if (lane == 0) wmax[wid] = __uint_as_float(wm);
        __syncthreads();
        float gb = wmax[0];
        #pragma unroll
        for (int t = 1; t < 8; t++) gb = fmaxf(gb, wmax[t]);
        if (myBest == gb){                      // only winning warp(s) scan
            int key = 0x7fffffff;
            #pragma unroll
            for (int t = 0; t < 32; t++)
                if (dst[t] == gb){
                    int i = tid*32 + t;
                    key = min(key, sPerm[i]*8192 + i);   // primary: ORIGINAL index (argmax tie rule)
                }
            atomicMin(&sArg[s & 1], key);
        }
        if (tid == 0) sArg[(s & 1) ^ 1] = 0x7fffffff;   // reset slot for next step
        __syncthreads();
        cur = sArg[s & 1] & 8191;               // permuted pos of lowest-orig-index winner
    }
}

// ---------------- ball query: 1 warp per centroid ----------------
__global__ void __launch_bounds__(1024) ballK(const float* __restrict__ xyz,
                                              const float* __restrict__ newXyz){
    extern __shared__ float sm[];
    float* sx = sm; float* sy = sm + NN; float* sz = sm + 2*NN;
    __shared__ int sIdx[32][KK];
    int b = blockIdx.x, tid = threadIdx.x, lane = tid & 31, w = tid >> 5;
    for (int i = tid; i < NN; i += 1024){
        sx[i] = xyz[((size_t)b*NN + i)*3 + 0];
        sy[i] = xyz[((size_t)b*NN + i)*3 + 1];
        sz[i] = xyz[((size_t)b*NN + i)*3 + 2];
    }
    __syncthreads();
    int s = blockIdx.y*32 + w;
    size_t co = ((size_t)b*SS + s)*3;
    float cx = newXyz[co], cy = newXyz[co+1], cz = newXyz[co+2];
    const float R2 = (float)(0.2*0.2);
    int cnt = 0;
    for (int base = 0; base < NN; base += 32){
        int i = base + lane;
        float dx = __fsub_rn(cx, sx[i]);
        float dy = __fsub_rn(cy, sy[i]);
        float dz = __fsub_rn(cz, sz[i]);
        float d = __fadd_rn(__fadd_rn(__fmul_rn(dx,dx), __fmul_rn(dy,dy)), __fmul_rn(dz,dz));
        bool in = !(d > R2);
        unsigned m = __ballot_sync(0xffffffffu, in);
        if (in){
            int r = cnt + __popc(m & ((1u << lane) - 1u));
            if (r < KK) sIdx[w][r] = i;
        }
        cnt += __popc(m);
        if (cnt >= KK) break;
    }
    __syncwarp();
    int v = (lane < cnt) ? sIdx[w][lane] : 0;
    int first = __shfl_sync(0xffffffffu, sIdx[w][0], 0);
    if (lane >= cnt) v = first;                 // pad with smallest in-radius index
    g_idx[((size_t)b*SS + s)*KK + lane] = v;
}

// ---------------- fused gather / affine+relu load + GEMM + BN stats ----------------
// block: 256 thr, tile PT positions x COUT channels, 4x8 register micro-tile
template<int CIN, int COUT, int TX, int TY, int PT, bool FIRST>
__global__ void __launch_bounds__(256) gemmK(const float* __restrict__ W,
                                             const float* __restrict__ bias,
                                             const float* __restrict__ xyz,
                                             const float* __restrict__ newXyz,
                                             int layer){
    constexpr int CP = 68;                       // padded k-stride (17 mod 8 == 1 -> conflict free)
    extern __shared__ float sm[];
    float* Ws = sm;                              // [COUT][CP]
    float* Vs = sm + COUT*CP;                    // [PT][CP]
    int tid = threadIdx.x;
    int P0 = blockIdx.x * PT;

    for (int e = tid; e < COUT*CP; e += 256){
        int c = e / CP, k = e - c*CP;
        Ws[e] = (k < CIN) ? W[c*CIN + k] : 0.0f;
    }
    if (FIRST){
        int w = tid >> 5, lane = tid & 31;
        for (int lp = w; lp < PT; lp += 8){
            int p = P0 + lp;
            int bb = p >> 15; int rem = p & 32767; int sIx = rem >> 5;
            int n = g_idx[p];
            const float* fr = &g_featT[((size_t)bb*NN + n)*CF];
            Vs[lp*CP + 3  + lane] = fr[lane];
            Vs[lp*CP + 35 + lane] = fr[32 + lane];
            if (lane < 3)
                Vs[lp*CP + lane] = __fsub_rn(xyz[((size_t)bb*NN + n)*3 + lane],
                                             newXyz[((size_t)bb*SS + sIx)*3 + lane]);
            if (lane == 3) Vs[lp*CP + 67] = 0.0f;
        }
    } else {
        const float* yin = (layer == 1) ? g_y0 : g_y1;
        const float* sc  = g_scale + (layer - 1)*128;
        const float* sh  = g_shift + (layer - 1)*128;
        for (int e = tid; e < PT*CP; e += 256){
            int lp = e / CP, k = e - lp*CP;
            float v = 0.0f;
            if (k < CIN){
                v = yin[(size_t)(P0 + lp)*CIN + k];
                v = fmaxf(fmaf(v, sc[k], sh[k]), 0.0f);   // fused BN + relu
            }
            Vs[e] = v;
        }
    }
    __syncthreads();

    int tx = tid % TX, ty = tid / TX;
    float acc[8][4];
    #pragma unroll
    for (int j = 0; j < 4; j++){
        float bj = bias[tx + TX*j];
        #pragma unroll
        for (int i = 0; i < 8; i++) acc[i][j] = bj;
    }
    #pragma unroll 1
    for (int k = 0; k < CP; k += 4){
        float4 wv[4];
        #pragma unroll
        for (int j = 0; j < 4; j++)
            wv[j] = *(const float4*)&Ws[(tx + TX*j)*CP + k];
        #pragma unroll
        for (int i = 0; i < 8; i++){
            float4 vv = *(const float4*)&Vs[(ty + TY*i)*CP + k];
            #pragma unroll
            for (int j = 0; j < 4; j++){
                acc[i][j] = fmaf(vv.x, wv[j].x, acc[i][j]);
                acc[i][j] = fmaf(vv.y, wv[j].y, acc[i][j]);
                acc[i][j] = fmaf(vv.z, wv[j].z, acc[i][j]);
                acc[i][j] = fmaf(vv.w, wv[j].w, acc[i][j]);
            }
        }
    }
    float* yout = (layer == 0) ? g_y0 : (layer == 1) ? g_y1 : g_y2;
    #pragma unroll
    for (int i = 0; i < 8; i++){
        size_t p = P0 + ty + TY*i;
        #pragma unroll
        for (int j = 0; j < 4; j++)
            yout[p*COUT + tx + TX*j] = acc[i][j];
    }

    // ---- fused BN statistics (no extra HBM pass) ----
    __syncthreads();                              // Ws/Vs dead -> reuse smem
    float* wsum = sm;                             // [8][TX][4]
    float* wssq = sm + 8*TX*4;                    // [8][TX][4]
    float ps[4], pss[4];
    #pragma unroll
    for (int j = 0; j < 4; j++){
        float s1 = 0.0f, s2 = 0.0f;
        #pragma unroll
        for (int i = 0; i < 8; i++){ float v = acc[i][j]; s1 += v; s2 = fmaf(v, v, s2); }
        ps[j] = s1; pss[j] = s2;
    }
    int ewid = tid >> 5, elane = tid & 31;
    if (TX == 16){                                // lanes tx and tx+16 share channels
        #pragma unroll
        for (int j = 0; j < 4; j++){
            ps[j]  += __shfl_down_sync(0xffffffffu, ps[j],  16);
            pss[j] += __shfl_down_sync(0xffffffffu, pss[j], 16);
        }
    }
    if (TX == 32 || elane < 16){
        #pragma unroll
        for (int j = 0; j < 4; j++){
            wsum[(ewid*TX + (elane % TX))*4 + j] = ps[j];
            wssq[(ewid*TX + (elane % TX))*4 + j] = pss[j];
        }
    }
    __syncthreads();
    if (tid < COUT){                              // channel c = txc + TX*j == tid
        int j = tid / TX, txc = tid % TX;
        double ds = 0.0, dss = 0.0;
        #pragma unroll
        for (int w = 0; w < 8; w++){              // fixed order: deterministic per CTA
            ds  += (double)wsum[(w*TX + txc)*4 + j];
            dss += (double)wssq[(w*TX + txc)*4 + j];
        }
        atomicAdd(&g_sum[layer*128 + tid], ds);
        atomicAdd(&g_sumsq[layer*128 + tid], dss);
    }
}

// ---------------- BN finalize ----------------
__global__ void zeroK(){
    int t = threadIdx.x;
    if (t < 384){ g_sum[t] = 0.0; g_sumsq[t] = 0.0; }
}

__global__ void finK(const float* __restrict__ g, const float* __restrict__ beta,
                     int layer, int cout){
    int c = threadIdx.x;
    if (c < cout){
        double n = (double)NPOS;
        double mean = g_sum[layer*128 + c] / n;
        double var  = g_sumsq[layer*128 + c] / n - mean*mean;
        float rstd = rsqrtf((float)var + 1e-5f);
        float gg = g[c];
        g_scale[layer*128 + c] = gg * rstd;
        g_shift[layer*128 + c] = beta[c] - (float)mean * rstd * gg;
    }
}

// ---------------- final BN+relu+max over nsample ----------------
__global__ void __launch_bounds__(128) maxK(float* __restrict__ outFeat){
    int bs = blockIdx.x, c = threadIdx.x;
    float sc = g_scale[2*128 + c], sh = g_shift[2*128 + c];
    const float* base = g_y2 + (size_t)bs*KK*128;
    float m = 0.0f;                               // relu outputs are >= 0
    #pragma unroll 4
    for (int k = 0; k < KK; k++)
        m = fmaxf(m, fmaxf(fmaf(base[k*128 + c], sc, sh), 0.0f));
    int b = bs >> 10, s = bs & 1023;
    outFeat[((size_t)b*128 + c)*SS + s] = m;
}

// ---------------- launch ----------------
extern "C" void kernel_launch(void* const* d_in, const int* in_sizes, int n_in,
                              void* d_out, int out_size){
    const float* xyz   = (const float*)d_in[0];
    const float* feat  = (const float*)d_in[1];
    const float* W0 = (const float*)d_in[2],  *b0 = (const float*)d_in[3];
    const float* g0 = (const float*)d_in[4],  *be0 = (const float*)d_in[5];
    const float* W1 = (const float*)d_in[6],  *b1 = (const float*)d_in[7];
    const float* g1 = (const float*)d_in[8],  *be1 = (const float*)d_in[9];
    const float* W2 = (const float*)d_in[10], *b2 = (const float*)d_in[11];
    const float* g2 = (const float*)d_in[12], *be2 = (const float*)d_in[13];

    float* outXyz  = (float*)d_out;               // (8,1024,3)
    float* outFeat = outXyz + (size_t)BB*SS*3;    // (8,128,1024)

    const int SMEM_PTS  = 3*NN*4;                 // 96 KB (ballK)
    const int SMEM_FPS  = 4*NN*4;                 // 128 KB (coords + perm)
    const int SMEM_GEMM = 192*68*4;               // 52224 B (same for all 3 layers)

    cudaFuncSetAttribute(fpsK,  cudaFuncAttributeMaxDynamicSharedMemorySize, SMEM_FPS);
    cudaFuncSetAttribute(ballK, cudaFuncAttributeMaxDynamicSharedMemorySize, SMEM_PTS);
    cudaFuncSetAttribute(gemmK<67,64,16,16,128,true>,   cudaFuncAttributeMaxDynamicSharedMemorySize, SMEM_GEMM);
    cudaFuncSetAttribute(gemmK<64,64,16,16,128,false>,  cudaFuncAttributeMaxDynamicSharedMemorySize, SMEM_GEMM);
    cudaFuncSetAttribute(gemmK<64,128,32,8,64,false>,   cudaFuncAttributeMaxDynamicSharedMemorySize, SMEM_GEMM);

    zeroK<<<1, 384>>>();
    transposeK<<<dim3(NN/32, CF/32, BB), dim3(32, 8)>>>(feat);
    bucketK<<<BB, 512>>>(xyz);
    fpsK<<<BB, 256, SMEM_FPS>>>(outXyz);
    ballK<<<dim3(BB, SS/32), 1024, SMEM_PTS>>>(xyz, outXyz);

    gemmK<67,64,16,16,128,true><<<NPOS/128, 256, SMEM_GEMM>>>(W0, b0, xyz, outXyz, 0);
    finK<<<1, 128>>>(g0, be0, 0, 64);

    gemmK<64,64,16,16,128,false><<<NPOS/128, 256, SMEM_GEMM>>>(W1, b1, xyz, outXyz, 1);
    finK<<<1, 128>>>(g1, be1, 1, 64);

    gemmK<64,128,32,8,64,false><<<NPOS/64, 256, SMEM_GEMM>>>(W2, b2, xyz, outXyz, 2);
    finK<<<1, 128>>>(g2, be2, 2, 128);

    maxK<<<BB*SS, 128>>>(outFeat);
}